// round 1
// baseline (speedup 1.0000x reference)
#include <cuda_runtime.h>

// DGMNet fused kernel: entire 3-layer DGM network in one kernel launch.
// Each CTA processes TM=32 batch rows through all layers; H and T=U*O1 live
// in shared memory; O2 carried in registers. Weights stream from L2.
//
// Input order (metadata): X, W_in, b_in, Wf, Uf, bf, Wu, Uu, bu,
//                         Wo1, Uo1, bo1, Wo2, bo2, W_out, b_out

#define NN       512
#define DIN      4
#define NLAYERS  3
#define TM       32
#define NTHREADS 512

__device__ __forceinline__ float sigmoidf_(float x) { return 1.0f / (1.0f + __expf(-x)); }
__device__ __forceinline__ float siluf_(float x)    { return x * sigmoidf_(x); }
__device__ __forceinline__ float tanhf_(float x)    { return 2.0f * sigmoidf_(2.0f * x) - 1.0f; }

// acc[m][j] += Hbuf[rbase+m][k] * Wg[k][c0+j], k = 0..511
__device__ __forceinline__ void gemm_acc(const float* __restrict__ Hbuf,
                                         const float* __restrict__ Wg,
                                         int rbase, int c0, float acc[8][4])
{
    #pragma unroll 2
    for (int k = 0; k < NN; k += 4) {
        float4 w0 = *(const float4*)(Wg + (size_t)(k + 0) * NN + c0);
        float4 w1 = *(const float4*)(Wg + (size_t)(k + 1) * NN + c0);
        float4 w2 = *(const float4*)(Wg + (size_t)(k + 2) * NN + c0);
        float4 w3 = *(const float4*)(Wg + (size_t)(k + 3) * NN + c0);
        #pragma unroll
        for (int m = 0; m < 8; m++) {
            float4 h = *(const float4*)(Hbuf + (rbase + m) * NN + k);
            acc[m][0] += h.x * w0.x + h.y * w1.x + h.z * w2.x + h.w * w3.x;
            acc[m][1] += h.x * w0.y + h.y * w1.y + h.z * w2.y + h.w * w3.y;
            acc[m][2] += h.x * w0.z + h.y * w1.z + h.z * w2.z + h.w * w3.z;
            acc[m][3] += h.x * w0.w + h.y * w1.w + h.z * w2.w + h.w * w3.w;
        }
    }
}

// acc[m][j] = bg[c0+j] + sum_q Xs[rbase+m][q] * Wg[q][c0+j]
__device__ __forceinline__ void init_xpart(const float* __restrict__ Xs,
                                           const float* __restrict__ Wg,
                                           const float* __restrict__ bg,
                                           int rbase, int c0, float acc[8][4])
{
    #pragma unroll
    for (int j = 0; j < 4; j++) {
        float bb = bg[c0 + j];
        #pragma unroll
        for (int m = 0; m < 8; m++) acc[m][j] = bb;
    }
    #pragma unroll
    for (int q = 0; q < DIN; q++) {
        float4 w = *(const float4*)(Wg + q * NN + c0);
        #pragma unroll
        for (int m = 0; m < 8; m++) {
            float xv = Xs[(rbase + m) * DIN + q];
            acc[m][0] += xv * w.x;
            acc[m][1] += xv * w.y;
            acc[m][2] += xv * w.z;
            acc[m][3] += xv * w.w;
        }
    }
}

extern "C" __global__ void __launch_bounds__(NTHREADS, 1)
dgm_fused_kernel(const float* __restrict__ X,
                 const float* __restrict__ W_in,  const float* __restrict__ b_in,
                 const float* __restrict__ Wf,    const float* __restrict__ Uf,
                 const float* __restrict__ bf,
                 const float* __restrict__ Wu,    const float* __restrict__ Uu,
                 const float* __restrict__ bu,
                 const float* __restrict__ Wo1,   const float* __restrict__ Uo1,
                 const float* __restrict__ bo1,
                 const float* __restrict__ Wo2,   const float* __restrict__ bo2,
                 const float* __restrict__ W_out, const float* __restrict__ b_out,
                 float* __restrict__ out)
{
    extern __shared__ float smem[];
    float* Hs = smem;                 // [TM][NN]
    float* Ts = smem + TM * NN;       // [TM][NN]
    float* Xs = smem + 2 * TM * NN;   // [TM][DIN]

    const int tid   = threadIdx.x;
    const int cg    = tid & 127;      // column group 0..127
    const int c0    = cg * 4;         // 4 consecutive columns
    const int rg    = tid >> 7;       // row group 0..3
    const int rbase = rg * 8;         // 8 rows per thread
    const long row0 = (long)blockIdx.x * TM;

    // Stage X tile
    if (tid < TM * DIN) {
        int r = tid / DIN, q = tid % DIN;
        Xs[r * DIN + q] = X[(row0 + r) * DIN + q];
    }
    __syncthreads();

    // H = silu(X @ W_in + b_in)
    #pragma unroll
    for (int m = 0; m < 8; m++) {
        int r = rbase + m;
        #pragma unroll
        for (int j = 0; j < 4; j++) {
            int c = c0 + j;
            float a = b_in[c];
            #pragma unroll
            for (int q = 0; q < DIN; q++) a += Xs[r * DIN + q] * W_in[q * NN + c];
            Hs[r * NN + c] = siluf_(a);
        }
    }
    __syncthreads();

    float acc[8][4];
    float carry[8][4];

    for (int i = 0; i < NLAYERS; i++) {
        const float* Uu_i  = Uu  + (size_t)i * NN * NN;
        const float* Uo1_i = Uo1 + (size_t)i * NN * NN;
        const float* Wo2_i = Wo2 + (size_t)i * NN * NN;
        const float* Uf_i  = Uf  + (size_t)i * NN * NN;
        const float* Wu_i  = Wu  + (size_t)i * DIN * NN;
        const float* Wo1_i = Wo1 + (size_t)i * DIN * NN;
        const float* Wf_i  = Wf  + (size_t)i * DIN * NN;
        const float* bu_i  = bu  + (size_t)i * NN;
        const float* bo1_i = bo1 + (size_t)i * NN;
        const float* bo2_i = bo2 + (size_t)i * NN;
        const float* bf_i  = bf  + (size_t)i * NN;

        // ---- Pass 1: U = sigmoid(X@Wu + H@Uu + bu) -> Ts
        init_xpart(Xs, Wu_i, bu_i, rbase, c0, acc);
        gemm_acc(Hs, Uu_i, rbase, c0, acc);
        #pragma unroll
        for (int m = 0; m < 8; m++) {
            float4 v;
            v.x = sigmoidf_(acc[m][0]);
            v.y = sigmoidf_(acc[m][1]);
            v.z = sigmoidf_(acc[m][2]);
            v.w = sigmoidf_(acc[m][3]);
            *(float4*)(Ts + (rbase + m) * NN + c0) = v;
        }
        // Each thread RMWs only its own Ts elements in pass 2 -> no sync needed.

        // ---- Pass 2: O1 = tanh(X@Wo1 + H@Uo1 + bo1);  Ts *= O1
        init_xpart(Xs, Wo1_i, bo1_i, rbase, c0, acc);
        gemm_acc(Hs, Uo1_i, rbase, c0, acc);
        #pragma unroll
        for (int m = 0; m < 8; m++) {
            float4 v = *(const float4*)(Ts + (rbase + m) * NN + c0);
            v.x *= tanhf_(acc[m][0]);
            v.y *= tanhf_(acc[m][1]);
            v.z *= tanhf_(acc[m][2]);
            v.w *= tanhf_(acc[m][3]);
            *(float4*)(Ts + (rbase + m) * NN + c0) = v;
        }
        __syncthreads();   // Ts fully written before pass 3 reads all k

        // ---- Pass 3: O2 = silu(Ts @ Wo2 + bo2) -> carry (registers)
        #pragma unroll
        for (int j = 0; j < 4; j++) {
            float bb = bo2_i[c0 + j];
            #pragma unroll
            for (int m = 0; m < 8; m++) acc[m][j] = bb;
        }
        gemm_acc(Ts, Wo2_i, rbase, c0, acc);
        #pragma unroll
        for (int m = 0; m < 8; m++)
            #pragma unroll
            for (int j = 0; j < 4; j++) carry[m][j] = siluf_(acc[m][j]);

        // ---- Pass 4: F = sigmoid(X@Wf + H@Uf + bf);  H = F*H + O2
        init_xpart(Xs, Wf_i, bf_i, rbase, c0, acc);
        gemm_acc(Hs, Uf_i, rbase, c0, acc);
        __syncthreads();   // all reads of old H complete before overwrite
        #pragma unroll
        for (int m = 0; m < 8; m++) {
            float4 h = *(const float4*)(Hs + (rbase + m) * NN + c0);
            h.x = sigmoidf_(acc[m][0]) * h.x + carry[m][0];
            h.y = sigmoidf_(acc[m][1]) * h.y + carry[m][1];
            h.z = sigmoidf_(acc[m][2]) * h.z + carry[m][2];
            h.w = sigmoidf_(acc[m][3]) * h.w + carry[m][3];
            *(float4*)(Hs + (rbase + m) * NN + c0) = h;
        }
        __syncthreads();   // new H visible to all before next layer
    }

    // ---- Output: out = silu(H @ W_out + b_out), one scalar per row.
    // 16 threads per row, each sums 32 elements, then segmented shuffle reduce.
    {
        const int lane16 = tid & 15;
        const int r      = tid >> 4;   // 0..31
        const int kb     = lane16 * 32;
        float s = 0.0f;
        #pragma unroll 8
        for (int k = kb; k < kb + 32; k++) s += Hs[r * NN + k] * W_out[k];
        #pragma unroll
        for (int off = 8; off > 0; off >>= 1)
            s += __shfl_down_sync(0xffffffffu, s, off, 16);
        if (lane16 == 0) out[row0 + r] = siluf_(s + b_out[0]);
    }
}

extern "C" void kernel_launch(void* const* d_in, const int* in_sizes, int n_in,
                              void* d_out, int out_size)
{
    const float* X     = (const float*)d_in[0];
    const float* W_in  = (const float*)d_in[1];
    const float* b_in  = (const float*)d_in[2];
    const float* Wf    = (const float*)d_in[3];
    const float* Uf    = (const float*)d_in[4];
    const float* bf    = (const float*)d_in[5];
    const float* Wu    = (const float*)d_in[6];
    const float* Uu    = (const float*)d_in[7];
    const float* bu    = (const float*)d_in[8];
    const float* Wo1   = (const float*)d_in[9];
    const float* Uo1   = (const float*)d_in[10];
    const float* bo1   = (const float*)d_in[11];
    const float* Wo2   = (const float*)d_in[12];
    const float* bo2   = (const float*)d_in[13];
    const float* W_out = (const float*)d_in[14];
    const float* b_out = (const float*)d_in[15];
    float* out = (float*)d_out;

    const int rows = in_sizes[0] / DIN;      // 131072
    const int grid = rows / TM;              // 4096

    const int smem_bytes = (2 * TM * NN + TM * DIN) * (int)sizeof(float); // ~128.5 KB
    cudaFuncSetAttribute(dgm_fused_kernel,
                         cudaFuncAttributeMaxDynamicSharedMemorySize, smem_bytes);

    dgm_fused_kernel<<<grid, NTHREADS, smem_bytes>>>(
        X, W_in, b_in, Wf, Uf, bf, Wu, Uu, bu,
        Wo1, Uo1, bo1, Wo2, bo2, W_out, b_out, out);
}

// round 2
// speedup vs baseline: 1.0009x; 1.0009x over previous
#include <cuda_runtime.h>

// DGMNet fused kernel: entire 3-layer DGM network in one kernel launch.
// Each CTA processes TM=32 batch rows through all layers; H and T=U*O1 live
// in shared memory; O2 carried in registers. Weights stream from L2.
//
// Input order (metadata): X, W_in, b_in, Wf, Uf, bf, Wu, Uu, bu,
//                         Wo1, Uo1, bo1, Wo2, bo2, W_out, b_out

#define NN       512
#define DIN      4
#define NLAYERS  3
#define TM       32
#define NTHREADS 512

__device__ __forceinline__ float sigmoidf_(float x) { return 1.0f / (1.0f + __expf(-x)); }
__device__ __forceinline__ float siluf_(float x)    { return x * sigmoidf_(x); }
__device__ __forceinline__ float tanhf_(float x)    { return 2.0f * sigmoidf_(2.0f * x) - 1.0f; }

// acc[m][j] += Hbuf[rbase+m][k] * Wg[k][c0+j], k = 0..511
__device__ __forceinline__ void gemm_acc(const float* __restrict__ Hbuf,
                                         const float* __restrict__ Wg,
                                         int rbase, int c0, float acc[8][4])
{
    #pragma unroll 2
    for (int k = 0; k < NN; k += 4) {
        float4 w0 = *(const float4*)(Wg + (size_t)(k + 0) * NN + c0);
        float4 w1 = *(const float4*)(Wg + (size_t)(k + 1) * NN + c0);
        float4 w2 = *(const float4*)(Wg + (size_t)(k + 2) * NN + c0);
        float4 w3 = *(const float4*)(Wg + (size_t)(k + 3) * NN + c0);
        #pragma unroll
        for (int m = 0; m < 8; m++) {
            float4 h = *(const float4*)(Hbuf + (rbase + m) * NN + k);
            acc[m][0] += h.x * w0.x + h.y * w1.x + h.z * w2.x + h.w * w3.x;
            acc[m][1] += h.x * w0.y + h.y * w1.y + h.z * w2.y + h.w * w3.y;
            acc[m][2] += h.x * w0.z + h.y * w1.z + h.z * w2.z + h.w * w3.z;
            acc[m][3] += h.x * w0.w + h.y * w1.w + h.z * w2.w + h.w * w3.w;
        }
    }
}

// acc[m][j] = bg[c0+j] + sum_q Xs[rbase+m][q] * Wg[q][c0+j]
__device__ __forceinline__ void init_xpart(const float* __restrict__ Xs,
                                           const float* __restrict__ Wg,
                                           const float* __restrict__ bg,
                                           int rbase, int c0, float acc[8][4])
{
    #pragma unroll
    for (int j = 0; j < 4; j++) {
        float bb = bg[c0 + j];
        #pragma unroll
        for (int m = 0; m < 8; m++) acc[m][j] = bb;
    }
    #pragma unroll
    for (int q = 0; q < DIN; q++) {
        float4 w = *(const float4*)(Wg + q * NN + c0);
        #pragma unroll
        for (int m = 0; m < 8; m++) {
            float xv = Xs[(rbase + m) * DIN + q];
            acc[m][0] += xv * w.x;
            acc[m][1] += xv * w.y;
            acc[m][2] += xv * w.z;
            acc[m][3] += xv * w.w;
        }
    }
}

extern "C" __global__ void __launch_bounds__(NTHREADS, 1)
dgm_fused_kernel(const float* __restrict__ X,
                 const float* __restrict__ W_in,  const float* __restrict__ b_in,
                 const float* __restrict__ Wf,    const float* __restrict__ Uf,
                 const float* __restrict__ bf,
                 const float* __restrict__ Wu,    const float* __restrict__ Uu,
                 const float* __restrict__ bu,
                 const float* __restrict__ Wo1,   const float* __restrict__ Uo1,
                 const float* __restrict__ bo1,
                 const float* __restrict__ Wo2,   const float* __restrict__ bo2,
                 const float* __restrict__ W_out, const float* __restrict__ b_out,
                 float* __restrict__ out)
{
    extern __shared__ float smem[];
    float* Hs = smem;                 // [TM][NN]
    float* Ts = smem + TM * NN;       // [TM][NN]
    float* Xs = smem + 2 * TM * NN;   // [TM][DIN]

    const int tid   = threadIdx.x;
    const int cg    = tid & 127;      // column group 0..127
    const int c0    = cg * 4;         // 4 consecutive columns
    const int rg    = tid >> 7;       // row group 0..3
    const int rbase = rg * 8;         // 8 rows per thread
    const long row0 = (long)blockIdx.x * TM;

    // Stage X tile
    if (tid < TM * DIN) {
        int r = tid / DIN, q = tid % DIN;
        Xs[r * DIN + q] = X[(row0 + r) * DIN + q];
    }
    __syncthreads();

    // H = silu(X @ W_in + b_in)
    #pragma unroll
    for (int m = 0; m < 8; m++) {
        int r = rbase + m;
        #pragma unroll
        for (int j = 0; j < 4; j++) {
            int c = c0 + j;
            float a = b_in[c];
            #pragma unroll
            for (int q = 0; q < DIN; q++) a += Xs[r * DIN + q] * W_in[q * NN + c];
            Hs[r * NN + c] = siluf_(a);
        }
    }
    __syncthreads();

    float acc[8][4];
    float carry[8][4];

    for (int i = 0; i < NLAYERS; i++) {
        const float* Uu_i  = Uu  + (size_t)i * NN * NN;
        const float* Uo1_i = Uo1 + (size_t)i * NN * NN;
        const float* Wo2_i = Wo2 + (size_t)i * NN * NN;
        const float* Uf_i  = Uf  + (size_t)i * NN * NN;
        const float* Wu_i  = Wu  + (size_t)i * DIN * NN;
        const float* Wo1_i = Wo1 + (size_t)i * DIN * NN;
        const float* Wf_i  = Wf  + (size_t)i * DIN * NN;
        const float* bu_i  = bu  + (size_t)i * NN;
        const float* bo1_i = bo1 + (size_t)i * NN;
        const float* bo2_i = bo2 + (size_t)i * NN;
        const float* bf_i  = bf  + (size_t)i * NN;

        // ---- Pass 1: U = sigmoid(X@Wu + H@Uu + bu) -> Ts
        init_xpart(Xs, Wu_i, bu_i, rbase, c0, acc);
        gemm_acc(Hs, Uu_i, rbase, c0, acc);
        #pragma unroll
        for (int m = 0; m < 8; m++) {
            float4 v;
            v.x = sigmoidf_(acc[m][0]);
            v.y = sigmoidf_(acc[m][1]);
            v.z = sigmoidf_(acc[m][2]);
            v.w = sigmoidf_(acc[m][3]);
            *(float4*)(Ts + (rbase + m) * NN + c0) = v;
        }
        // Each thread RMWs only its own Ts elements in pass 2 -> no sync needed.

        // ---- Pass 2: O1 = tanh(X@Wo1 + H@Uo1 + bo1);  Ts *= O1
        init_xpart(Xs, Wo1_i, bo1_i, rbase, c0, acc);
        gemm_acc(Hs, Uo1_i, rbase, c0, acc);
        #pragma unroll
        for (int m = 0; m < 8; m++) {
            float4 v = *(const float4*)(Ts + (rbase + m) * NN + c0);
            v.x *= tanhf_(acc[m][0]);
            v.y *= tanhf_(acc[m][1]);
            v.z *= tanhf_(acc[m][2]);
            v.w *= tanhf_(acc[m][3]);
            *(float4*)(Ts + (rbase + m) * NN + c0) = v;
        }
        __syncthreads();   // Ts fully written before pass 3 reads all k

        // ---- Pass 3: O2 = silu(Ts @ Wo2 + bo2) -> carry (registers)
        #pragma unroll
        for (int j = 0; j < 4; j++) {
            float bb = bo2_i[c0 + j];
            #pragma unroll
            for (int m = 0; m < 8; m++) acc[m][j] = bb;
        }
        gemm_acc(Ts, Wo2_i, rbase, c0, acc);
        #pragma unroll
        for (int m = 0; m < 8; m++)
            #pragma unroll
            for (int j = 0; j < 4; j++) carry[m][j] = siluf_(acc[m][j]);

        // ---- Pass 4: F = sigmoid(X@Wf + H@Uf + bf);  H = F*H + O2
        init_xpart(Xs, Wf_i, bf_i, rbase, c0, acc);
        gemm_acc(Hs, Uf_i, rbase, c0, acc);
        __syncthreads();   // all reads of old H complete before overwrite
        #pragma unroll
        for (int m = 0; m < 8; m++) {
            float4 h = *(const float4*)(Hs + (rbase + m) * NN + c0);
            h.x = sigmoidf_(acc[m][0]) * h.x + carry[m][0];
            h.y = sigmoidf_(acc[m][1]) * h.y + carry[m][1];
            h.z = sigmoidf_(acc[m][2]) * h.z + carry[m][2];
            h.w = sigmoidf_(acc[m][3]) * h.w + carry[m][3];
            *(float4*)(Hs + (rbase + m) * NN + c0) = h;
        }
        __syncthreads();   // new H visible to all before next layer
    }

    // ---- Output: out = silu(H @ W_out + b_out), one scalar per row.
    // 16 threads per row, each sums 32 elements, then segmented shuffle reduce.
    {
        const int lane16 = tid & 15;
        const int r      = tid >> 4;   // 0..31
        const int kb     = lane16 * 32;
        float s = 0.0f;
        #pragma unroll 8
        for (int k = kb; k < kb + 32; k++) s += Hs[r * NN + k] * W_out[k];
        #pragma unroll
        for (int off = 8; off > 0; off >>= 1)
            s += __shfl_down_sync(0xffffffffu, s, off, 16);
        if (lane16 == 0) out[row0 + r] = siluf_(s + b_out[0]);
    }
}

extern "C" void kernel_launch(void* const* d_in, const int* in_sizes, int n_in,
                              void* d_out, int out_size)
{
    const float* X     = (const float*)d_in[0];
    const float* W_in  = (const float*)d_in[1];
    const float* b_in  = (const float*)d_in[2];
    const float* Wf    = (const float*)d_in[3];
    const float* Uf    = (const float*)d_in[4];
    const float* bf    = (const float*)d_in[5];
    const float* Wu    = (const float*)d_in[6];
    const float* Uu    = (const float*)d_in[7];
    const float* bu    = (const float*)d_in[8];
    const float* Wo1   = (const float*)d_in[9];
    const float* Uo1   = (const float*)d_in[10];
    const float* bo1   = (const float*)d_in[11];
    const float* Wo2   = (const float*)d_in[12];
    const float* bo2   = (const float*)d_in[13];
    const float* W_out = (const float*)d_in[14];
    const float* b_out = (const float*)d_in[15];
    float* out = (float*)d_out;

    const int rows = in_sizes[0] / DIN;      // 131072
    const int grid = rows / TM;              // 4096

    const int smem_bytes = (2 * TM * NN + TM * DIN) * (int)sizeof(float); // ~128.5 KB
    cudaFuncSetAttribute(dgm_fused_kernel,
                         cudaFuncAttributeMaxDynamicSharedMemorySize, smem_bytes);

    dgm_fused_kernel<<<grid, NTHREADS, smem_bytes>>>(
        X, W_in, b_in, Wf, Uf, bf, Wu, Uu, bu,
        Wo1, Uo1, bo1, Wo2, bo2, W_out, b_out, out);
}

// round 3
// speedup vs baseline: 1.0010x; 1.0001x over previous
#include <cuda_runtime.h>

// DGMNet fused kernel: entire 3-layer DGM network in one kernel launch.
// Each CTA processes TM=32 batch rows through all layers; H and T=U*O1 live
// in shared memory; O2 carried in registers. Weights stream from L2.
//
// Input order (metadata): X, W_in, b_in, Wf, Uf, bf, Wu, Uu, bu,
//                         Wo1, Uo1, bo1, Wo2, bo2, W_out, b_out

#define NN       512
#define DIN      4
#define NLAYERS  3
#define TM       32
#define NTHREADS 512

__device__ __forceinline__ float sigmoidf_(float x) { return 1.0f / (1.0f + __expf(-x)); }
__device__ __forceinline__ float siluf_(float x)    { return x * sigmoidf_(x); }
__device__ __forceinline__ float tanhf_(float x)    { return 2.0f * sigmoidf_(2.0f * x) - 1.0f; }

// acc[m][j] += Hbuf[rbase+m][k] * Wg[k][c0+j], k = 0..511
__device__ __forceinline__ void gemm_acc(const float* __restrict__ Hbuf,
                                         const float* __restrict__ Wg,
                                         int rbase, int c0, float acc[8][4])
{
    #pragma unroll 2
    for (int k = 0; k < NN; k += 4) {
        float4 w0 = *(const float4*)(Wg + (size_t)(k + 0) * NN + c0);
        float4 w1 = *(const float4*)(Wg + (size_t)(k + 1) * NN + c0);
        float4 w2 = *(const float4*)(Wg + (size_t)(k + 2) * NN + c0);
        float4 w3 = *(const float4*)(Wg + (size_t)(k + 3) * NN + c0);
        #pragma unroll
        for (int m = 0; m < 8; m++) {
            float4 h = *(const float4*)(Hbuf + (rbase + m) * NN + k);
            acc[m][0] += h.x * w0.x + h.y * w1.x + h.z * w2.x + h.w * w3.x;
            acc[m][1] += h.x * w0.y + h.y * w1.y + h.z * w2.y + h.w * w3.y;
            acc[m][2] += h.x * w0.z + h.y * w1.z + h.z * w2.z + h.w * w3.z;
            acc[m][3] += h.x * w0.w + h.y * w1.w + h.z * w2.w + h.w * w3.w;
        }
    }
}

// acc[m][j] = bg[c0+j] + sum_q Xs[rbase+m][q] * Wg[q][c0+j]
__device__ __forceinline__ void init_xpart(const float* __restrict__ Xs,
                                           const float* __restrict__ Wg,
                                           const float* __restrict__ bg,
                                           int rbase, int c0, float acc[8][4])
{
    #pragma unroll
    for (int j = 0; j < 4; j++) {
        float bb = bg[c0 + j];
        #pragma unroll
        for (int m = 0; m < 8; m++) acc[m][j] = bb;
    }
    #pragma unroll
    for (int q = 0; q < DIN; q++) {
        float4 w = *(const float4*)(Wg + q * NN + c0);
        #pragma unroll
        for (int m = 0; m < 8; m++) {
            float xv = Xs[(rbase + m) * DIN + q];
            acc[m][0] += xv * w.x;
            acc[m][1] += xv * w.y;
            acc[m][2] += xv * w.z;
            acc[m][3] += xv * w.w;
        }
    }
}

extern "C" __global__ void __launch_bounds__(NTHREADS, 1)
dgm_fused_kernel(const float* __restrict__ X,
                 const float* __restrict__ W_in,  const float* __restrict__ b_in,
                 const float* __restrict__ Wf,    const float* __restrict__ Uf,
                 const float* __restrict__ bf,
                 const float* __restrict__ Wu,    const float* __restrict__ Uu,
                 const float* __restrict__ bu,
                 const float* __restrict__ Wo1,   const float* __restrict__ Uo1,
                 const float* __restrict__ bo1,
                 const float* __restrict__ Wo2,   const float* __restrict__ bo2,
                 const float* __restrict__ W_out, const float* __restrict__ b_out,
                 float* __restrict__ out)
{
    extern __shared__ float smem[];
    float* Hs = smem;                 // [TM][NN]
    float* Ts = smem + TM * NN;       // [TM][NN]
    float* Xs = smem + 2 * TM * NN;   // [TM][DIN]

    const int tid   = threadIdx.x;
    const int cg    = tid & 127;      // column group 0..127
    const int c0    = cg * 4;         // 4 consecutive columns
    const int rg    = tid >> 7;       // row group 0..3
    const int rbase = rg * 8;         // 8 rows per thread
    const long row0 = (long)blockIdx.x * TM;

    // Stage X tile
    if (tid < TM * DIN) {
        int r = tid / DIN, q = tid % DIN;
        Xs[r * DIN + q] = X[(row0 + r) * DIN + q];
    }
    __syncthreads();

    // H = silu(X @ W_in + b_in)
    #pragma unroll
    for (int m = 0; m < 8; m++) {
        int r = rbase + m;
        #pragma unroll
        for (int j = 0; j < 4; j++) {
            int c = c0 + j;
            float a = b_in[c];
            #pragma unroll
            for (int q = 0; q < DIN; q++) a += Xs[r * DIN + q] * W_in[q * NN + c];
            Hs[r * NN + c] = siluf_(a);
        }
    }
    __syncthreads();

    float acc[8][4];
    float carry[8][4];

    for (int i = 0; i < NLAYERS; i++) {
        const float* Uu_i  = Uu  + (size_t)i * NN * NN;
        const float* Uo1_i = Uo1 + (size_t)i * NN * NN;
        const float* Wo2_i = Wo2 + (size_t)i * NN * NN;
        const float* Uf_i  = Uf  + (size_t)i * NN * NN;
        const float* Wu_i  = Wu  + (size_t)i * DIN * NN;
        const float* Wo1_i = Wo1 + (size_t)i * DIN * NN;
        const float* Wf_i  = Wf  + (size_t)i * DIN * NN;
        const float* bu_i  = bu  + (size_t)i * NN;
        const float* bo1_i = bo1 + (size_t)i * NN;
        const float* bo2_i = bo2 + (size_t)i * NN;
        const float* bf_i  = bf  + (size_t)i * NN;

        // ---- Pass 1: U = sigmoid(X@Wu + H@Uu + bu) -> Ts
        init_xpart(Xs, Wu_i, bu_i, rbase, c0, acc);
        gemm_acc(Hs, Uu_i, rbase, c0, acc);
        #pragma unroll
        for (int m = 0; m < 8; m++) {
            float4 v;
            v.x = sigmoidf_(acc[m][0]);
            v.y = sigmoidf_(acc[m][1]);
            v.z = sigmoidf_(acc[m][2]);
            v.w = sigmoidf_(acc[m][3]);
            *(float4*)(Ts + (rbase + m) * NN + c0) = v;
        }
        // Each thread RMWs only its own Ts elements in pass 2 -> no sync needed.

        // ---- Pass 2: O1 = tanh(X@Wo1 + H@Uo1 + bo1);  Ts *= O1
        init_xpart(Xs, Wo1_i, bo1_i, rbase, c0, acc);
        gemm_acc(Hs, Uo1_i, rbase, c0, acc);
        #pragma unroll
        for (int m = 0; m < 8; m++) {
            float4 v = *(const float4*)(Ts + (rbase + m) * NN + c0);
            v.x *= tanhf_(acc[m][0]);
            v.y *= tanhf_(acc[m][1]);
            v.z *= tanhf_(acc[m][2]);
            v.w *= tanhf_(acc[m][3]);
            *(float4*)(Ts + (rbase + m) * NN + c0) = v;
        }
        __syncthreads();   // Ts fully written before pass 3 reads all k

        // ---- Pass 3: O2 = silu(Ts @ Wo2 + bo2) -> carry (registers)
        #pragma unroll
        for (int j = 0; j < 4; j++) {
            float bb = bo2_i[c0 + j];
            #pragma unroll
            for (int m = 0; m < 8; m++) acc[m][j] = bb;
        }
        gemm_acc(Ts, Wo2_i, rbase, c0, acc);
        #pragma unroll
        for (int m = 0; m < 8; m++)
            #pragma unroll
            for (int j = 0; j < 4; j++) carry[m][j] = siluf_(acc[m][j]);

        // ---- Pass 4: F = sigmoid(X@Wf + H@Uf + bf);  H = F*H + O2
        init_xpart(Xs, Wf_i, bf_i, rbase, c0, acc);
        gemm_acc(Hs, Uf_i, rbase, c0, acc);
        __syncthreads();   // all reads of old H complete before overwrite
        #pragma unroll
        for (int m = 0; m < 8; m++) {
            float4 h = *(const float4*)(Hs + (rbase + m) * NN + c0);
            h.x = sigmoidf_(acc[m][0]) * h.x + carry[m][0];
            h.y = sigmoidf_(acc[m][1]) * h.y + carry[m][1];
            h.z = sigmoidf_(acc[m][2]) * h.z + carry[m][2];
            h.w = sigmoidf_(acc[m][3]) * h.w + carry[m][3];
            *(float4*)(Hs + (rbase + m) * NN + c0) = h;
        }
        __syncthreads();   // new H visible to all before next layer
    }

    // ---- Output: out = silu(H @ W_out + b_out), one scalar per row.
    // 16 threads per row, each sums 32 elements, then segmented shuffle reduce.
    {
        const int lane16 = tid & 15;
        const int r      = tid >> 4;   // 0..31
        const int kb     = lane16 * 32;
        float s = 0.0f;
        #pragma unroll 8
        for (int k = kb; k < kb + 32; k++) s += Hs[r * NN + k] * W_out[k];
        #pragma unroll
        for (int off = 8; off > 0; off >>= 1)
            s += __shfl_down_sync(0xffffffffu, s, off, 16);
        if (lane16 == 0) out[row0 + r] = siluf_(s + b_out[0]);
    }
}

extern "C" void kernel_launch(void* const* d_in, const int* in_sizes, int n_in,
                              void* d_out, int out_size)
{
    const float* X     = (const float*)d_in[0];
    const float* W_in  = (const float*)d_in[1];
    const float* b_in  = (const float*)d_in[2];
    const float* Wf    = (const float*)d_in[3];
    const float* Uf    = (const float*)d_in[4];
    const float* bf    = (const float*)d_in[5];
    const float* Wu    = (const float*)d_in[6];
    const float* Uu    = (const float*)d_in[7];
    const float* bu    = (const float*)d_in[8];
    const float* Wo1   = (const float*)d_in[9];
    const float* Uo1   = (const float*)d_in[10];
    const float* bo1   = (const float*)d_in[11];
    const float* Wo2   = (const float*)d_in[12];
    const float* bo2   = (const float*)d_in[13];
    const float* W_out = (const float*)d_in[14];
    const float* b_out = (const float*)d_in[15];
    float* out = (float*)d_out;

    const int rows = in_sizes[0] / DIN;      // 131072
    const int grid = rows / TM;              // 4096

    const int smem_bytes = (2 * TM * NN + TM * DIN) * (int)sizeof(float); // ~128.5 KB
    cudaFuncSetAttribute(dgm_fused_kernel,
                         cudaFuncAttributeMaxDynamicSharedMemorySize, smem_bytes);

    dgm_fused_kernel<<<grid, NTHREADS, smem_bytes>>>(
        X, W_in, b_in, Wf, Uf, bf, Wu, Uu, bu,
        Wo1, Uo1, bo1, Wo2, bo2, W_out, b_out, out);
}

// round 4
// speedup vs baseline: 1.0010x; 1.0000x over previous
#include <cuda_runtime.h>

// DGMNet fused kernel: entire 3-layer DGM network in one kernel launch.
// Each CTA processes TM=32 batch rows through all layers; H and T=U*O1 live
// in shared memory; O2 carried in registers. Weights stream from L2.
//
// Input order (metadata): X, W_in, b_in, Wf, Uf, bf, Wu, Uu, bu,
//                         Wo1, Uo1, bo1, Wo2, bo2, W_out, b_out

#define NN       512
#define DIN      4
#define NLAYERS  3
#define TM       32
#define NTHREADS 512

__device__ __forceinline__ float sigmoidf_(float x) { return 1.0f / (1.0f + __expf(-x)); }
__device__ __forceinline__ float siluf_(float x)    { return x * sigmoidf_(x); }
__device__ __forceinline__ float tanhf_(float x)    { return 2.0f * sigmoidf_(2.0f * x) - 1.0f; }

// acc[m][j] += Hbuf[rbase+m][k] * Wg[k][c0+j], k = 0..511
__device__ __forceinline__ void gemm_acc(const float* __restrict__ Hbuf,
                                         const float* __restrict__ Wg,
                                         int rbase, int c0, float acc[8][4])
{
    #pragma unroll 2
    for (int k = 0; k < NN; k += 4) {
        float4 w0 = *(const float4*)(Wg + (size_t)(k + 0) * NN + c0);
        float4 w1 = *(const float4*)(Wg + (size_t)(k + 1) * NN + c0);
        float4 w2 = *(const float4*)(Wg + (size_t)(k + 2) * NN + c0);
        float4 w3 = *(const float4*)(Wg + (size_t)(k + 3) * NN + c0);
        #pragma unroll
        for (int m = 0; m < 8; m++) {
            float4 h = *(const float4*)(Hbuf + (rbase + m) * NN + k);
            acc[m][0] += h.x * w0.x + h.y * w1.x + h.z * w2.x + h.w * w3.x;
            acc[m][1] += h.x * w0.y + h.y * w1.y + h.z * w2.y + h.w * w3.y;
            acc[m][2] += h.x * w0.z + h.y * w1.z + h.z * w2.z + h.w * w3.z;
            acc[m][3] += h.x * w0.w + h.y * w1.w + h.z * w2.w + h.w * w3.w;
        }
    }
}

// acc[m][j] = bg[c0+j] + sum_q Xs[rbase+m][q] * Wg[q][c0+j]
__device__ __forceinline__ void init_xpart(const float* __restrict__ Xs,
                                           const float* __restrict__ Wg,
                                           const float* __restrict__ bg,
                                           int rbase, int c0, float acc[8][4])
{
    #pragma unroll
    for (int j = 0; j < 4; j++) {
        float bb = bg[c0 + j];
        #pragma unroll
        for (int m = 0; m < 8; m++) acc[m][j] = bb;
    }
    #pragma unroll
    for (int q = 0; q < DIN; q++) {
        float4 w = *(const float4*)(Wg + q * NN + c0);
        #pragma unroll
        for (int m = 0; m < 8; m++) {
            float xv = Xs[(rbase + m) * DIN + q];
            acc[m][0] += xv * w.x;
            acc[m][1] += xv * w.y;
            acc[m][2] += xv * w.z;
            acc[m][3] += xv * w.w;
        }
    }
}

extern "C" __global__ void __launch_bounds__(NTHREADS, 1)
dgm_fused_kernel(const float* __restrict__ X,
                 const float* __restrict__ W_in,  const float* __restrict__ b_in,
                 const float* __restrict__ Wf,    const float* __restrict__ Uf,
                 const float* __restrict__ bf,
                 const float* __restrict__ Wu,    const float* __restrict__ Uu,
                 const float* __restrict__ bu,
                 const float* __restrict__ Wo1,   const float* __restrict__ Uo1,
                 const float* __restrict__ bo1,
                 const float* __restrict__ Wo2,   const float* __restrict__ bo2,
                 const float* __restrict__ W_out, const float* __restrict__ b_out,
                 float* __restrict__ out)
{
    extern __shared__ float smem[];
    float* Hs = smem;                 // [TM][NN]
    float* Ts = smem + TM * NN;       // [TM][NN]
    float* Xs = smem + 2 * TM * NN;   // [TM][DIN]

    const int tid   = threadIdx.x;
    const int cg    = tid & 127;      // column group 0..127
    const int c0    = cg * 4;         // 4 consecutive columns
    const int rg    = tid >> 7;       // row group 0..3
    const int rbase = rg * 8;         // 8 rows per thread
    const long row0 = (long)blockIdx.x * TM;

    // Stage X tile
    if (tid < TM * DIN) {
        int r = tid / DIN, q = tid % DIN;
        Xs[r * DIN + q] = X[(row0 + r) * DIN + q];
    }
    __syncthreads();

    // H = silu(X @ W_in + b_in)
    #pragma unroll
    for (int m = 0; m < 8; m++) {
        int r = rbase + m;
        #pragma unroll
        for (int j = 0; j < 4; j++) {
            int c = c0 + j;
            float a = b_in[c];
            #pragma unroll
            for (int q = 0; q < DIN; q++) a += Xs[r * DIN + q] * W_in[q * NN + c];
            Hs[r * NN + c] = siluf_(a);
        }
    }
    __syncthreads();

    float acc[8][4];
    float carry[8][4];

    for (int i = 0; i < NLAYERS; i++) {
        const float* Uu_i  = Uu  + (size_t)i * NN * NN;
        const float* Uo1_i = Uo1 + (size_t)i * NN * NN;
        const float* Wo2_i = Wo2 + (size_t)i * NN * NN;
        const float* Uf_i  = Uf  + (size_t)i * NN * NN;
        const float* Wu_i  = Wu  + (size_t)i * DIN * NN;
        const float* Wo1_i = Wo1 + (size_t)i * DIN * NN;
        const float* Wf_i  = Wf  + (size_t)i * DIN * NN;
        const float* bu_i  = bu  + (size_t)i * NN;
        const float* bo1_i = bo1 + (size_t)i * NN;
        const float* bo2_i = bo2 + (size_t)i * NN;
        const float* bf_i  = bf  + (size_t)i * NN;

        // ---- Pass 1: U = sigmoid(X@Wu + H@Uu + bu) -> Ts
        init_xpart(Xs, Wu_i, bu_i, rbase, c0, acc);
        gemm_acc(Hs, Uu_i, rbase, c0, acc);
        #pragma unroll
        for (int m = 0; m < 8; m++) {
            float4 v;
            v.x = sigmoidf_(acc[m][0]);
            v.y = sigmoidf_(acc[m][1]);
            v.z = sigmoidf_(acc[m][2]);
            v.w = sigmoidf_(acc[m][3]);
            *(float4*)(Ts + (rbase + m) * NN + c0) = v;
        }
        // Each thread RMWs only its own Ts elements in pass 2 -> no sync needed.

        // ---- Pass 2: O1 = tanh(X@Wo1 + H@Uo1 + bo1);  Ts *= O1
        init_xpart(Xs, Wo1_i, bo1_i, rbase, c0, acc);
        gemm_acc(Hs, Uo1_i, rbase, c0, acc);
        #pragma unroll
        for (int m = 0; m < 8; m++) {
            float4 v = *(const float4*)(Ts + (rbase + m) * NN + c0);
            v.x *= tanhf_(acc[m][0]);
            v.y *= tanhf_(acc[m][1]);
            v.z *= tanhf_(acc[m][2]);
            v.w *= tanhf_(acc[m][3]);
            *(float4*)(Ts + (rbase + m) * NN + c0) = v;
        }
        __syncthreads();   // Ts fully written before pass 3 reads all k

        // ---- Pass 3: O2 = silu(Ts @ Wo2 + bo2) -> carry (registers)
        #pragma unroll
        for (int j = 0; j < 4; j++) {
            float bb = bo2_i[c0 + j];
            #pragma unroll
            for (int m = 0; m < 8; m++) acc[m][j] = bb;
        }
        gemm_acc(Ts, Wo2_i, rbase, c0, acc);
        #pragma unroll
        for (int m = 0; m < 8; m++)
            #pragma unroll
            for (int j = 0; j < 4; j++) carry[m][j] = siluf_(acc[m][j]);

        // ---- Pass 4: F = sigmoid(X@Wf + H@Uf + bf);  H = F*H + O2
        init_xpart(Xs, Wf_i, bf_i, rbase, c0, acc);
        gemm_acc(Hs, Uf_i, rbase, c0, acc);
        __syncthreads();   // all reads of old H complete before overwrite
        #pragma unroll
        for (int m = 0; m < 8; m++) {
            float4 h = *(const float4*)(Hs + (rbase + m) * NN + c0);
            h.x = sigmoidf_(acc[m][0]) * h.x + carry[m][0];
            h.y = sigmoidf_(acc[m][1]) * h.y + carry[m][1];
            h.z = sigmoidf_(acc[m][2]) * h.z + carry[m][2];
            h.w = sigmoidf_(acc[m][3]) * h.w + carry[m][3];
            *(float4*)(Hs + (rbase + m) * NN + c0) = h;
        }
        __syncthreads();   // new H visible to all before next layer
    }

    // ---- Output: out = silu(H @ W_out + b_out), one scalar per row.
    // 16 threads per row, each sums 32 elements, then segmented shuffle reduce.
    {
        const int lane16 = tid & 15;
        const int r      = tid >> 4;   // 0..31
        const int kb     = lane16 * 32;
        float s = 0.0f;
        #pragma unroll 8
        for (int k = kb; k < kb + 32; k++) s += Hs[r * NN + k] * W_out[k];
        #pragma unroll
        for (int off = 8; off > 0; off >>= 1)
            s += __shfl_down_sync(0xffffffffu, s, off, 16);
        if (lane16 == 0) out[row0 + r] = siluf_(s + b_out[0]);
    }
}

extern "C" void kernel_launch(void* const* d_in, const int* in_sizes, int n_in,
                              void* d_out, int out_size)
{
    const float* X     = (const float*)d_in[0];
    const float* W_in  = (const float*)d_in[1];
    const float* b_in  = (const float*)d_in[2];
    const float* Wf    = (const float*)d_in[3];
    const float* Uf    = (const float*)d_in[4];
    const float* bf    = (const float*)d_in[5];
    const float* Wu    = (const float*)d_in[6];
    const float* Uu    = (const float*)d_in[7];
    const float* bu    = (const float*)d_in[8];
    const float* Wo1   = (const float*)d_in[9];
    const float* Uo1   = (const float*)d_in[10];
    const float* bo1   = (const float*)d_in[11];
    const float* Wo2   = (const float*)d_in[12];
    const float* bo2   = (const float*)d_in[13];
    const float* W_out = (const float*)d_in[14];
    const float* b_out = (const float*)d_in[15];
    float* out = (float*)d_out;

    const int rows = in_sizes[0] / DIN;      // 131072
    const int grid = rows / TM;              // 4096

    const int smem_bytes = (2 * TM * NN + TM * DIN) * (int)sizeof(float); // ~128.5 KB
    cudaFuncSetAttribute(dgm_fused_kernel,
                         cudaFuncAttributeMaxDynamicSharedMemorySize, smem_bytes);

    dgm_fused_kernel<<<grid, NTHREADS, smem_bytes>>>(
        X, W_in, b_in, Wf, Uf, bf, Wu, Uu, bu,
        Wo1, Uo1, bo1, Wo2, bo2, W_out, b_out, out);
}